// round 4
// baseline (speedup 1.0000x reference)
#include <cuda_runtime.h>
#include <cuda_bf16.h>
#include <math.h>

// ---------------- problem constants ----------------
#define N_ENT 50000
#define DIM   128
#define E_NUM 200000
#define S_NUM 20000
#define NREL  200
#define NBASES 4
#define YCOLS 640          // 4 bases * 128 + 128 root columns

// ---------------- device scratch (no runtime alloc allowed) ----------------
__device__ float g_X[2][N_ENT * DIM];          // ping-pong node features (2 x 25.6 MB)
__device__ float g_Y[(size_t)N_ENT * YCOLS];   // basis projections + root (128 MB)
__device__ float g_agg[N_ENT * DIM];           // edge aggregation (25.6 MB)
__device__ float g_cnt[N_ENT];
__device__ float g_inv[N_ENT];
__device__ float g_W[DIM * YCOLS];             // packed [Din][4*Dout + Dout] weight
__device__ float g_T[NREL * DIM];              // DAD @ rel_ctx
__device__ float g_R[NREL * DIM];              // relu(T @ Wgcn)

// ---------------- small helper kernels ----------------
__global__ void k_zero_cnt() {
    int i = blockIdx.x * blockDim.x + threadIdx.x;
    if (i < N_ENT) g_cnt[i] = 0.0f;
}

__global__ void k_zero_agg() {
    int i = blockIdx.x * blockDim.x + threadIdx.x;   // float4 index
    if (i < N_ENT * (DIM / 4)) ((float4*)g_agg)[i] = make_float4(0.f, 0.f, 0.f, 0.f);
}

__global__ void k_count(const int* __restrict__ ei) {
    int e = blockIdx.x * blockDim.x + threadIdx.x;
    if (e < E_NUM) atomicAdd(&g_cnt[ei[E_NUM + e]], 1.0f);
}

__global__ void k_inv() {
    int i = blockIdx.x * blockDim.x + threadIdx.x;
    if (i < N_ENT) g_inv[i] = 1.0f / fmaxf(g_cnt[i], 1.0f);
}

__global__ void k_gather(const int* __restrict__ entity, const float* __restrict__ ectx) {
    int idx = blockIdx.x * blockDim.x + threadIdx.x;
    if (idx >= N_ENT * DIM) return;
    int n = idx >> 7, d = idx & 127;
    g_X[0][idx] = ectx[(size_t)entity[n] * DIM + d];
}

// pack basis [B, Din, Dout] + root [Din, Dout] into W [Din][B*Dout + Dout]
__global__ void k_pack(const float* __restrict__ basis, const float* __restrict__ root) {
    int idx = blockIdx.x * blockDim.x + threadIdx.x;
    if (idx >= DIM * YCOLS) return;
    int i = idx / YCOLS, c = idx % YCOLS;
    float v;
    if (c < NBASES * DIM) {
        int b = c >> 7, o = c & 127;
        v = basis[((size_t)b * DIM + i) * DIM + o];
    } else {
        v = root[(size_t)i * DIM + (c - NBASES * DIM)];
    }
    g_W[idx] = v;
}

// ---------------- GEMM: Y[M,640] = X[M,128] @ W[128,640] ----------------
// 64x64 tile, 256 threads, 4x4 microtile, K chunked by 64.
__global__ void __launch_bounds__(256) k_gemm(int xbuf, int Mrows) {
    __shared__ float As[64 * 64];   // [m][k]
    __shared__ float Bs[64 * 64];   // [k][n]
    const float* A = g_X[xbuf];
    int tid = threadIdx.x;
    int tx = tid & 15, ty = tid >> 4;
    int m0 = blockIdx.x * 64;
    int n0 = blockIdx.y * 64;

    float4 acc[4];
    #pragma unroll
    for (int i = 0; i < 4; i++) acc[i] = make_float4(0.f, 0.f, 0.f, 0.f);

    for (int kc = 0; kc < 2; kc++) {
        // load A tile (guard rows)
        #pragma unroll
        for (int t = 0; t < 4; t++) {
            int q = tid + t * 256;
            int row = q >> 4;      // 0..63
            int c4  = q & 15;      // float4 within 64 k-floats
            float4 v = make_float4(0.f, 0.f, 0.f, 0.f);
            if (m0 + row < Mrows)
                v = *(const float4*)(A + (size_t)(m0 + row) * DIM + kc * 64 + c4 * 4);
            *(float4*)(As + row * 64 + c4 * 4) = v;
        }
        // load B tile (always in-bounds: K=128, N=640)
        #pragma unroll
        for (int t = 0; t < 4; t++) {
            int q = tid + t * 256;
            int kr = q >> 4;
            int c4 = q & 15;
            float4 v = *(const float4*)(g_W + (size_t)(kc * 64 + kr) * YCOLS + n0 + c4 * 4);
            *(float4*)(Bs + kr * 64 + c4 * 4) = v;
        }
        __syncthreads();

        #pragma unroll
        for (int kk = 0; kk < 16; kk++) {
            float4 a[4], b[4];
            #pragma unroll
            for (int i = 0; i < 4; i++)
                a[i] = *(float4*)(As + (ty * 4 + i) * 64 + kk * 4);
            #pragma unroll
            for (int j = 0; j < 4; j++)
                b[j] = *(float4*)(Bs + (kk * 4 + j) * 64 + tx * 4);
            #pragma unroll
            for (int i = 0; i < 4; i++) {
                acc[i].x += a[i].x * b[0].x + a[i].y * b[1].x + a[i].z * b[2].x + a[i].w * b[3].x;
                acc[i].y += a[i].x * b[0].y + a[i].y * b[1].y + a[i].z * b[2].y + a[i].w * b[3].y;
                acc[i].z += a[i].x * b[0].z + a[i].y * b[1].z + a[i].z * b[2].z + a[i].w * b[3].z;
                acc[i].w += a[i].x * b[0].w + a[i].y * b[1].w + a[i].z * b[2].w + a[i].w * b[3].w;
            }
        }
        __syncthreads();
    }

    #pragma unroll
    for (int i = 0; i < 4; i++) {
        int row = m0 + ty * 4 + i;
        if (row < Mrows)
            *(float4*)(g_Y + (size_t)row * YCOLS + n0 + tx * 4) = acc[i];
    }
}

// ---------------- edge message + aggregation ----------------
// one warp per edge: msg = norm * sum_b att[type][b] * Y[src][b*128 .. b*128+127]
__global__ void __launch_bounds__(256) k_edge(const int* __restrict__ ei,
                                              const int* __restrict__ etype,
                                              const float* __restrict__ enorm,
                                              const float* __restrict__ att) {
    int e = blockIdx.x * 8 + (threadIdx.x >> 5);
    if (e >= E_NUM) return;
    int lane = threadIdx.x & 31;

    int src = ei[e];
    int dst = ei[E_NUM + e];
    int t   = etype[e];
    float nrm = enorm[e];
    float4 c = ((const float4*)att)[t];   // att[t][0..3]
    float c0 = nrm * c.x, c1 = nrm * c.y, c2 = nrm * c.z, c3 = nrm * c.w;

    const float4* Ys = (const float4*)(g_Y + (size_t)src * YCOLS);
    float4 y0 = Ys[0 * 32 + lane];
    float4 y1 = Ys[1 * 32 + lane];
    float4 y2 = Ys[2 * 32 + lane];
    float4 y3 = Ys[3 * 32 + lane];

    float4 m;
    m.x = c0 * y0.x + c1 * y1.x + c2 * y2.x + c3 * y3.x;
    m.y = c0 * y0.y + c1 * y1.y + c2 * y2.y + c3 * y3.y;
    m.z = c0 * y0.z + c1 * y1.z + c2 * y2.z + c3 * y3.z;
    m.w = c0 * y0.w + c1 * y1.w + c2 * y2.w + c3 * y3.w;

    float* out = g_agg + (size_t)dst * DIM + lane * 4;
    atomicAdd(out + 0, m.x);
    atomicAdd(out + 1, m.y);
    atomicAdd(out + 2, m.z);
    atomicAdd(out + 3, m.w);
}

// ---------------- combine: Xnext = relu(agg*inv + Yroot + bias) ----------------
__global__ void k_combine(int obuf, const float* __restrict__ bias) {
    int idx = blockIdx.x * blockDim.x + threadIdx.x;   // float4 index over N_ENT*32
    if (idx >= N_ENT * (DIM / 4)) return;
    int n = idx >> 5, c4 = idx & 31;
    float inv = g_inv[n];
    float4 a = *(float4*)(g_agg + (size_t)n * DIM + c4 * 4);
    float4 r = *(const float4*)(g_Y + (size_t)n * YCOLS + NBASES * DIM + c4 * 4);
    float4 b = *(const float4*)(bias + c4 * 4);
    float4 o;
    o.x = fmaxf(a.x * inv + r.x + b.x, 0.f);
    o.y = fmaxf(a.y * inv + r.y + b.y, 0.f);
    o.z = fmaxf(a.z * inv + r.z + b.z, 0.f);
    o.w = fmaxf(a.w * inv + r.w + b.w, 0.f);
    *(float4*)(g_X[obuf] + (size_t)n * DIM + c4 * 4) = o;
}

// ---------------- relation path (tiny) ----------------
__global__ void k_relT(const float* __restrict__ DAD, const float* __restrict__ rctx) {
    int idx = blockIdx.x * blockDim.x + threadIdx.x;
    if (idx >= NREL * DIM) return;
    int r = idx >> 7, o = idx & 127;
    float s = 0.f;
    for (int k = 0; k < NREL; k++)
        s += DAD[r * NREL + k] * rctx[k * DIM + o];
    g_T[idx] = s;
}

__global__ void k_relR(const float* __restrict__ W) {
    int idx = blockIdx.x * blockDim.x + threadIdx.x;
    if (idx >= NREL * DIM) return;
    int r = idx >> 7, o = idx & 127;
    float s = 0.f;
    for (int k = 0; k < DIM; k++)
        s += g_T[r * DIM + k] * W[k * DIM + o];
    g_R[idx] = fmaxf(s, 0.f);
}

// ---------------- final gated gather ----------------
__global__ void k_out(const int* __restrict__ samples,
                      const float* __restrict__ ent_emb,
                      const float* __restrict__ rel_emb,
                      const float* __restrict__ gate_e,
                      const float* __restrict__ gate_r,
                      int x2buf, float* __restrict__ out) {
    int idx = blockIdx.x * blockDim.x + threadIdx.x;
    if (idx >= S_NUM * DIM) return;
    int s = idx >> 7, d = idx & 127;
    int h = samples[s * 3 + 0];
    int r = samples[s * 3 + 1];
    int t = samples[s * 3 + 2];
    float ge = 1.0f / (1.0f + expf(-gate_e[d]));
    float gr = 1.0f / (1.0f + expf(-gate_r[d]));
    const float* X2 = g_X[x2buf];
    out[idx] = ge * ent_emb[(size_t)h * DIM + d] + (1.0f - ge) * X2[(size_t)h * DIM + d];
    out[S_NUM * DIM + idx] = gr * rel_emb[(size_t)r * DIM + d] + (1.0f - gr) * g_R[(size_t)r * DIM + d];
    out[2 * S_NUM * DIM + idx] = ge * ent_emb[(size_t)t * DIM + d] + (1.0f - ge) * X2[(size_t)t * DIM + d];
}

// ---------------- launch ----------------
extern "C" void kernel_launch(void* const* d_in, const int* in_sizes, int n_in,
                              void* d_out, int out_size) {
    const int*   entity    = (const int*)d_in[0];
    const int*   edge_index= (const int*)d_in[1];
    const int*   edge_type = (const int*)d_in[2];
    const float* edge_norm = (const float*)d_in[3];
    const int*   samples   = (const int*)d_in[4];
    const float* DAD       = (const float*)d_in[5];
    const float* ent_emb   = (const float*)d_in[6];
    const float* rel_emb   = (const float*)d_in[7];
    const float* ectx      = (const float*)d_in[8];
    const float* rctx      = (const float*)d_in[9];
    const float* gcnW      = (const float*)d_in[10];
    const float* gate_e    = (const float*)d_in[11];
    const float* gate_r    = (const float*)d_in[12];
    const float* basis1    = (const float*)d_in[13];
    const float* att1      = (const float*)d_in[14];
    const float* root1     = (const float*)d_in[15];
    const float* bias1     = (const float*)d_in[16];
    const float* basis2    = (const float*)d_in[17];
    const float* att2      = (const float*)d_in[18];
    const float* root2     = (const float*)d_in[19];
    const float* bias2     = (const float*)d_in[20];
    float* out = (float*)d_out;

    const int THR = 256;
    dim3 gemm_grid((N_ENT + 63) / 64, YCOLS / 64);

    // degree counts (shared by both layers)
    k_zero_cnt<<<(N_ENT + THR - 1) / THR, THR>>>();
    k_count<<<(E_NUM + THR - 1) / THR, THR>>>(edge_index);
    k_inv<<<(N_ENT + THR - 1) / THR, THR>>>();

    // initial features
    k_gather<<<(N_ENT * DIM + THR - 1) / THR, THR>>>(entity, ectx);

    // ---- layer 1 ----
    k_pack<<<(DIM * YCOLS + THR - 1) / THR, THR>>>(basis1, root1);
    k_gemm<<<gemm_grid, THR>>>(0, N_ENT);
    k_zero_agg<<<(N_ENT * (DIM / 4) + THR - 1) / THR, THR>>>();
    k_edge<<<(E_NUM + 7) / 8, THR>>>(edge_index, edge_type, edge_norm, att1);
    k_combine<<<(N_ENT * (DIM / 4) + THR - 1) / THR, THR>>>(1, bias1);

    // ---- layer 2 ----
    k_pack<<<(DIM * YCOLS + THR - 1) / THR, THR>>>(basis2, root2);
    k_gemm<<<gemm_grid, THR>>>(1, N_ENT);
    k_zero_agg<<<(N_ENT * (DIM / 4) + THR - 1) / THR, THR>>>();
    k_edge<<<(E_NUM + 7) / 8, THR>>>(edge_index, edge_type, edge_norm, att2);
    k_combine<<<(N_ENT * (DIM / 4) + THR - 1) / THR, THR>>>(0, bias2);

    // ---- relation path ----
    k_relT<<<(NREL * DIM + THR - 1) / THR, THR>>>(DAD, rctx);
    k_relR<<<(NREL * DIM + THR - 1) / THR, THR>>>(gcnW);

    // ---- output ----
    k_out<<<(S_NUM * DIM + THR - 1) / THR, THR>>>(samples, ent_emb, rel_emb,
                                                  gate_e, gate_r, 0, out);
}

// round 5
// speedup vs baseline: 2.7089x; 2.7089x over previous
#include <cuda_runtime.h>
#include <cuda_bf16.h>
#include <math.h>

// ---------------- problem constants ----------------
#define N_ENT 50000
#define DIM   128
#define E_NUM 200000
#define S_NUM 20000
#define NREL  200
#define NBASES 4
#define YCOLS 640          // 4 bases * 128 + 128 root columns

// ---------------- device scratch (no runtime alloc allowed) ----------------
__device__ float g_X[2][N_ENT * DIM];          // ping-pong node features
__device__ float g_Y[(size_t)N_ENT * YCOLS];   // basis projections + root
__device__ float g_agg[N_ENT * DIM];           // edge aggregation
__device__ float g_cnt[N_ENT];
__device__ float g_inv[N_ENT];
__device__ float g_W[DIM * YCOLS];             // packed [Din][4*Dout + Dout] weight
__device__ float g_T[NREL * DIM];              // DAD @ rel_ctx
__device__ float g_R[NREL * DIM];              // relu(T @ Wgcn)

// ---------------- helpers ----------------
__device__ __forceinline__ unsigned f2tf32(float x) {
    unsigned u;
    asm("cvt.rna.tf32.f32 %0, %1;" : "=r"(u) : "f"(x));
    return u;
}

// ---------------- small helper kernels ----------------
__global__ void k_zero_cnt() {
    int i = blockIdx.x * blockDim.x + threadIdx.x;
    if (i < N_ENT) g_cnt[i] = 0.0f;
}

__global__ void k_zero_agg() {
    int i = blockIdx.x * blockDim.x + threadIdx.x;   // float4 index
    if (i < N_ENT * (DIM / 4)) ((float4*)g_agg)[i] = make_float4(0.f, 0.f, 0.f, 0.f);
}

__global__ void k_count(const int* __restrict__ ei) {
    int e = blockIdx.x * blockDim.x + threadIdx.x;
    if (e < E_NUM) atomicAdd(&g_cnt[ei[E_NUM + e]], 1.0f);
}

__global__ void k_inv() {
    int i = blockIdx.x * blockDim.x + threadIdx.x;
    if (i < N_ENT) g_inv[i] = 1.0f / fmaxf(g_cnt[i], 1.0f);
}

__global__ void k_gather(const int* __restrict__ entity, const float* __restrict__ ectx) {
    int idx = blockIdx.x * blockDim.x + threadIdx.x;
    if (idx >= N_ENT * DIM) return;
    int n = idx >> 7, d = idx & 127;
    g_X[0][idx] = ectx[(size_t)entity[n] * DIM + d];
}

// pack basis [B, Din, Dout] + root [Din, Dout] into W [Din][B*Dout + Dout]
__global__ void k_pack(const float* __restrict__ basis, const float* __restrict__ root) {
    int idx = blockIdx.x * blockDim.x + threadIdx.x;
    if (idx >= DIM * YCOLS) return;
    int i = idx / YCOLS, c = idx % YCOLS;
    float v;
    if (c < NBASES * DIM) {
        int b = c >> 7, o = c & 127;
        v = basis[((size_t)b * DIM + i) * DIM + o];
    } else {
        v = root[(size_t)i * DIM + (c - NBASES * DIM)];
    }
    g_W[idx] = v;
}

// ---------------- tf32 tensor-core GEMM: Y[M,640] = X[M,128] @ W[128,640] ----------------
// CTA tile 128x128, 8 warps (4x2), warp tile 32x64, mma.m16n8k8.tf32.
// Smem stride 36 words -> fragment-load bank index (4g+tig)%32, conflict-free.
#define SMSTRIDE 36

__global__ void __launch_bounds__(256, 2) k_gemm_tf32(int xbuf, int Mrows) {
    __shared__ unsigned As[128 * SMSTRIDE];   // [m][k], tf32 bits
    __shared__ unsigned Bt[128 * SMSTRIDE];   // [n][k], tf32 bits (B transposed)

    const float* A = g_X[xbuf];
    int tid = threadIdx.x;
    int lane = tid & 31, wid = tid >> 5;
    int warp_m = wid & 3, warp_n = wid >> 2;
    int g = lane >> 2, tig = lane & 3;
    int m0 = blockIdx.x * 128, n0 = blockIdx.y * 128;

    float d[2][8][4];
    #pragma unroll
    for (int mi = 0; mi < 2; mi++)
        #pragma unroll
        for (int ni = 0; ni < 8; ni++)
            #pragma unroll
            for (int q = 0; q < 4; q++) d[mi][ni][q] = 0.0f;

    #pragma unroll 1
    for (int c = 0; c < 4; c++) {
        int k0 = c * 32;
        // A chunk: 128 rows x 32 k (coalesced float4 loads)
        #pragma unroll
        for (int t = 0; t < 4; t++) {
            int idx = tid + t * 256;
            int row = idx >> 3, c4 = idx & 7;
            float4 v = make_float4(0.f, 0.f, 0.f, 0.f);
            if (m0 + row < Mrows)
                v = *(const float4*)(A + (size_t)(m0 + row) * DIM + k0 + c4 * 4);
            unsigned* p = As + row * SMSTRIDE + c4 * 4;
            p[0] = f2tf32(v.x); p[1] = f2tf32(v.y);
            p[2] = f2tf32(v.z); p[3] = f2tf32(v.w);
        }
        // B chunk: 32 k-rows x 128 n -> store transposed [n][k]
        #pragma unroll
        for (int t = 0; t < 4; t++) {
            int idx = tid + t * 256;
            int kr = idx & 31, c4 = idx >> 5;
            float4 v = *(const float4*)(g_W + (size_t)(k0 + kr) * YCOLS + n0 + c4 * 4);
            Bt[(c4 * 4 + 0) * SMSTRIDE + kr] = f2tf32(v.x);
            Bt[(c4 * 4 + 1) * SMSTRIDE + kr] = f2tf32(v.y);
            Bt[(c4 * 4 + 2) * SMSTRIDE + kr] = f2tf32(v.z);
            Bt[(c4 * 4 + 3) * SMSTRIDE + kr] = f2tf32(v.w);
        }
        __syncthreads();

        #pragma unroll
        for (int kk = 0; kk < 4; kk++) {
            unsigned a[2][4], b[8][2];
            #pragma unroll
            for (int mi = 0; mi < 2; mi++) {
                int br = warp_m * 32 + mi * 16;
                a[mi][0] = As[(br + g) * SMSTRIDE + kk * 8 + tig];
                a[mi][1] = As[(br + g + 8) * SMSTRIDE + kk * 8 + tig];
                a[mi][2] = As[(br + g) * SMSTRIDE + kk * 8 + tig + 4];
                a[mi][3] = As[(br + g + 8) * SMSTRIDE + kk * 8 + tig + 4];
            }
            #pragma unroll
            for (int ni = 0; ni < 8; ni++) {
                int bn = warp_n * 64 + ni * 8;
                b[ni][0] = Bt[(bn + g) * SMSTRIDE + kk * 8 + tig];
                b[ni][1] = Bt[(bn + g) * SMSTRIDE + kk * 8 + tig + 4];
            }
            #pragma unroll
            for (int mi = 0; mi < 2; mi++)
                #pragma unroll
                for (int ni = 0; ni < 8; ni++) {
                    asm volatile(
                        "mma.sync.aligned.m16n8k8.row.col.f32.tf32.tf32.f32 "
                        "{%0,%1,%2,%3}, {%4,%5,%6,%7}, {%8,%9}, {%0,%1,%2,%3};"
                        : "+f"(d[mi][ni][0]), "+f"(d[mi][ni][1]),
                          "+f"(d[mi][ni][2]), "+f"(d[mi][ni][3])
                        : "r"(a[mi][0]), "r"(a[mi][1]), "r"(a[mi][2]), "r"(a[mi][3]),
                          "r"(b[ni][0]), "r"(b[ni][1]));
                }
        }
        __syncthreads();
    }

    // store: c0/c1 -> (row, 2tig), c2/c3 -> (row+8, 2tig)
    #pragma unroll
    for (int mi = 0; mi < 2; mi++) {
        int r0 = m0 + warp_m * 32 + mi * 16 + g;
        #pragma unroll
        for (int ni = 0; ni < 8; ni++) {
            int col = n0 + warp_n * 64 + ni * 8 + tig * 2;
            if (r0 < Mrows)
                *(float2*)(g_Y + (size_t)r0 * YCOLS + col) =
                    make_float2(d[mi][ni][0], d[mi][ni][1]);
            if (r0 + 8 < Mrows)
                *(float2*)(g_Y + (size_t)(r0 + 8) * YCOLS + col) =
                    make_float2(d[mi][ni][2], d[mi][ni][3]);
        }
    }
}

// ---------------- edge message + aggregation ----------------
// one warp per edge: msg = norm * sum_b att[type][b] * Y[src][b*128 .. b*128+127]
__global__ void __launch_bounds__(256) k_edge(const int* __restrict__ ei,
                                              const int* __restrict__ etype,
                                              const float* __restrict__ enorm,
                                              const float* __restrict__ att) {
    int e = blockIdx.x * 8 + (threadIdx.x >> 5);
    if (e >= E_NUM) return;
    int lane = threadIdx.x & 31;

    int src = __ldg(ei + e);
    int dst = __ldg(ei + E_NUM + e);
    int t   = __ldg(etype + e);
    float nrm = __ldg(enorm + e);
    float4 c = __ldg((const float4*)att + t);   // att[t][0..3]
    float c0 = nrm * c.x, c1 = nrm * c.y, c2 = nrm * c.z, c3 = nrm * c.w;

    const float4* Ys = (const float4*)(g_Y + (size_t)src * YCOLS);
    float4 y0 = Ys[0 * 32 + lane];
    float4 y1 = Ys[1 * 32 + lane];
    float4 y2 = Ys[2 * 32 + lane];
    float4 y3 = Ys[3 * 32 + lane];

    float4 m;
    m.x = c0 * y0.x + c1 * y1.x + c2 * y2.x + c3 * y3.x;
    m.y = c0 * y0.y + c1 * y1.y + c2 * y2.y + c3 * y3.y;
    m.z = c0 * y0.z + c1 * y1.z + c2 * y2.z + c3 * y3.z;
    m.w = c0 * y0.w + c1 * y1.w + c2 * y2.w + c3 * y3.w;

    float* out = g_agg + (size_t)dst * DIM + lane * 4;
    asm volatile("red.global.add.v4.f32 [%0], {%1,%2,%3,%4};"
                 :: "l"(out), "f"(m.x), "f"(m.y), "f"(m.z), "f"(m.w)
                 : "memory");
}

// ---------------- combine: Xnext = relu(agg*inv + Yroot + bias) ----------------
__global__ void k_combine(int obuf, const float* __restrict__ bias) {
    int idx = blockIdx.x * blockDim.x + threadIdx.x;   // float4 index over N_ENT*32
    if (idx >= N_ENT * (DIM / 4)) return;
    int n = idx >> 5, c4 = idx & 31;
    float inv = g_inv[n];
    float4 a = *(float4*)(g_agg + (size_t)n * DIM + c4 * 4);
    float4 r = *(const float4*)(g_Y + (size_t)n * YCOLS + NBASES * DIM + c4 * 4);
    float4 b = *(const float4*)(bias + c4 * 4);
    float4 o;
    o.x = fmaxf(a.x * inv + r.x + b.x, 0.f);
    o.y = fmaxf(a.y * inv + r.y + b.y, 0.f);
    o.z = fmaxf(a.z * inv + r.z + b.z, 0.f);
    o.w = fmaxf(a.w * inv + r.w + b.w, 0.f);
    *(float4*)(g_X[obuf] + (size_t)n * DIM + c4 * 4) = o;
}

// ---------------- relation path (tiny) ----------------
__global__ void k_relT(const float* __restrict__ DAD, const float* __restrict__ rctx) {
    int idx = blockIdx.x * blockDim.x + threadIdx.x;
    if (idx >= NREL * DIM) return;
    int r = idx >> 7, o = idx & 127;
    float s = 0.f;
    for (int k = 0; k < NREL; k++)
        s += DAD[r * NREL + k] * rctx[k * DIM + o];
    g_T[idx] = s;
}

__global__ void k_relR(const float* __restrict__ W) {
    int idx = blockIdx.x * blockDim.x + threadIdx.x;
    if (idx >= NREL * DIM) return;
    int r = idx >> 7, o = idx & 127;
    float s = 0.f;
    for (int k = 0; k < DIM; k++)
        s += g_T[r * DIM + k] * W[k * DIM + o];
    g_R[idx] = fmaxf(s, 0.f);
}

// ---------------- final gated gather ----------------
__global__ void k_out(const int* __restrict__ samples,
                      const float* __restrict__ ent_emb,
                      const float* __restrict__ rel_emb,
                      const float* __restrict__ gate_e,
                      const float* __restrict__ gate_r,
                      int x2buf, float* __restrict__ out) {
    int idx = blockIdx.x * blockDim.x + threadIdx.x;
    if (idx >= S_NUM * DIM) return;
    int s = idx >> 7, d = idx & 127;
    int h = samples[s * 3 + 0];
    int r = samples[s * 3 + 1];
    int t = samples[s * 3 + 2];
    float ge = 1.0f / (1.0f + expf(-gate_e[d]));
    float gr = 1.0f / (1.0f + expf(-gate_r[d]));
    const float* X2 = g_X[x2buf];
    out[idx] = ge * ent_emb[(size_t)h * DIM + d] + (1.0f - ge) * X2[(size_t)h * DIM + d];
    out[S_NUM * DIM + idx] = gr * rel_emb[(size_t)r * DIM + d] + (1.0f - gr) * g_R[(size_t)r * DIM + d];
    out[2 * S_NUM * DIM + idx] = ge * ent_emb[(size_t)t * DIM + d] + (1.0f - ge) * X2[(size_t)t * DIM + d];
}

// ---------------- launch ----------------
extern "C" void kernel_launch(void* const* d_in, const int* in_sizes, int n_in,
                              void* d_out, int out_size) {
    const int*   entity    = (const int*)d_in[0];
    const int*   edge_index= (const int*)d_in[1];
    const int*   edge_type = (const int*)d_in[2];
    const float* edge_norm = (const float*)d_in[3];
    const int*   samples   = (const int*)d_in[4];
    const float* DAD       = (const float*)d_in[5];
    const float* ent_emb   = (const float*)d_in[6];
    const float* rel_emb   = (const float*)d_in[7];
    const float* ectx      = (const float*)d_in[8];
    const float* rctx      = (const float*)d_in[9];
    const float* gcnW      = (const float*)d_in[10];
    const float* gate_e    = (const float*)d_in[11];
    const float* gate_r    = (const float*)d_in[12];
    const float* basis1    = (const float*)d_in[13];
    const float* att1      = (const float*)d_in[14];
    const float* root1     = (const float*)d_in[15];
    const float* bias1     = (const float*)d_in[16];
    const float* basis2    = (const float*)d_in[17];
    const float* att2      = (const float*)d_in[18];
    const float* root2     = (const float*)d_in[19];
    const float* bias2     = (const float*)d_in[20];
    float* out = (float*)d_out;

    const int THR = 256;
    dim3 gemm_grid((N_ENT + 127) / 128, YCOLS / 128);

    // degree counts (shared by both layers)
    k_zero_cnt<<<(N_ENT + THR - 1) / THR, THR>>>();
    k_count<<<(E_NUM + THR - 1) / THR, THR>>>(edge_index);
    k_inv<<<(N_ENT + THR - 1) / THR, THR>>>();

    // initial features
    k_gather<<<(N_ENT * DIM + THR - 1) / THR, THR>>>(entity, ectx);

    // ---- layer 1 ----
    k_pack<<<(DIM * YCOLS + THR - 1) / THR, THR>>>(basis1, root1);
    k_gemm_tf32<<<gemm_grid, THR>>>(0, N_ENT);
    k_zero_agg<<<(N_ENT * (DIM / 4) + THR - 1) / THR, THR>>>();
    k_edge<<<(E_NUM + 7) / 8, THR>>>(edge_index, edge_type, edge_norm, att1);
    k_combine<<<(N_ENT * (DIM / 4) + THR - 1) / THR, THR>>>(1, bias1);

    // ---- layer 2 ----
    k_pack<<<(DIM * YCOLS + THR - 1) / THR, THR>>>(basis2, root2);
    k_gemm_tf32<<<gemm_grid, THR>>>(1, N_ENT);
    k_zero_agg<<<(N_ENT * (DIM / 4) + THR - 1) / THR, THR>>>();
    k_edge<<<(E_NUM + 7) / 8, THR>>>(edge_index, edge_type, edge_norm, att2);
    k_combine<<<(N_ENT * (DIM / 4) + THR - 1) / THR, THR>>>(0, bias2);

    // ---- relation path ----
    k_relT<<<(NREL * DIM + THR - 1) / THR, THR>>>(DAD, rctx);
    k_relR<<<(NREL * DIM + THR - 1) / THR, THR>>>(gcnW);

    // ---- output ----
    k_out<<<(S_NUM * DIM + THR - 1) / THR, THR>>>(samples, ent_emb, rel_emb,
                                                  gate_e, gate_r, 0, out);
}

// round 6
// speedup vs baseline: 2.8481x; 1.0514x over previous
#include <cuda_runtime.h>
#include <cuda_bf16.h>
#include <math.h>

// ---------------- problem constants ----------------
#define N_ENT 50000
#define DIM   128
#define E_NUM 200000
#define S_NUM 20000
#define NREL  200
#define NBASES 4
#define YCOLS 640          // 4 bases * 128 + 128 root columns

// ---------------- device scratch (no runtime alloc allowed) ----------------
__device__ float g_X[2][N_ENT * DIM];              // ping-pong node features
// basis projections, bf16, interleaved: [node][d/4][basis][4]  (1024 B/node)
__device__ __nv_bfloat16 g_Yb[(size_t)N_ENT * NBASES * DIM];
__device__ float g_Yr[(size_t)N_ENT * DIM];        // root projection, fp32
__device__ float g_agg[N_ENT * DIM];               // edge aggregation
__device__ float g_cnt[N_ENT];
__device__ float g_inv[N_ENT];
__device__ float g_W[DIM * YCOLS];                 // packed [Din][4*Dout + Dout]
__device__ float g_T[NREL * DIM];                  // DAD @ rel_ctx
__device__ float g_R[NREL * DIM];                  // relu(T @ Wgcn)

// ---------------- helpers ----------------
__device__ __forceinline__ unsigned f2tf32(float x) {
    unsigned u;
    asm("cvt.rna.tf32.f32 %0, %1;" : "=r"(u) : "f"(x));
    return u;
}

// ---------------- small helper kernels ----------------
__global__ void k_zero_cnt() {
    int i = blockIdx.x * blockDim.x + threadIdx.x;
    if (i < N_ENT) g_cnt[i] = 0.0f;
}

__global__ void k_zero_agg() {
    int i = blockIdx.x * blockDim.x + threadIdx.x;   // float4 index
    if (i < N_ENT * (DIM / 4)) ((float4*)g_agg)[i] = make_float4(0.f, 0.f, 0.f, 0.f);
}

__global__ void k_count(const int* __restrict__ ei) {
    int e = blockIdx.x * blockDim.x + threadIdx.x;
    if (e < E_NUM) atomicAdd(&g_cnt[ei[E_NUM + e]], 1.0f);
}

__global__ void k_inv() {
    int i = blockIdx.x * blockDim.x + threadIdx.x;
    if (i < N_ENT) g_inv[i] = 1.0f / fmaxf(g_cnt[i], 1.0f);
}

// vectorized gather: one float4 per thread, one warp per node
__global__ void k_gather(const int* __restrict__ entity, const float* __restrict__ ectx) {
    int idx = blockIdx.x * blockDim.x + threadIdx.x;   // float4 index
    if (idx >= N_ENT * (DIM / 4)) return;
    int n = idx >> 5, c = idx & 31;
    ((float4*)g_X[0])[idx] = ((const float4*)ectx)[(size_t)entity[n] * 32 + c];
}

// pack basis [B, Din, Dout] + root [Din, Dout] into W [Din][B*Dout + Dout]
__global__ void k_pack(const float* __restrict__ basis, const float* __restrict__ root) {
    int idx = blockIdx.x * blockDim.x + threadIdx.x;
    if (idx >= DIM * YCOLS) return;
    int i = idx / YCOLS, c = idx % YCOLS;
    float v;
    if (c < NBASES * DIM) {
        int b = c >> 7, o = c & 127;
        v = basis[((size_t)b * DIM + i) * DIM + o];
    } else {
        v = root[(size_t)i * DIM + (c - NBASES * DIM)];
    }
    g_W[idx] = v;
}

// ---------------- tf32 tensor-core GEMM: [M,128] @ [128,640] ----------------
// CTA tile 128x128, 8 warps (4x2), warp tile 32x64, mma.m16n8k8.tf32.
// blockIdx.y 0..3 -> basis b (bf16 interleaved output), 4 -> root (fp32 output).
#define SMSTRIDE 36

__global__ void __launch_bounds__(256, 2) k_gemm_tf32(int xbuf, int Mrows) {
    __shared__ unsigned As[128 * SMSTRIDE];   // [m][k], tf32 bits
    __shared__ unsigned Bt[128 * SMSTRIDE];   // [n][k], tf32 bits (B transposed)

    const float* A = g_X[xbuf];
    int tid = threadIdx.x;
    int lane = tid & 31, wid = tid >> 5;
    int warp_m = wid & 3, warp_n = wid >> 2;
    int g = lane >> 2, tig = lane & 3;
    int m0 = blockIdx.x * 128, n0 = blockIdx.y * 128;

    float d[2][8][4];
    #pragma unroll
    for (int mi = 0; mi < 2; mi++)
        #pragma unroll
        for (int ni = 0; ni < 8; ni++)
            #pragma unroll
            for (int q = 0; q < 4; q++) d[mi][ni][q] = 0.0f;

    #pragma unroll 1
    for (int c = 0; c < 4; c++) {
        int k0 = c * 32;
        // A chunk: 128 rows x 32 k
        #pragma unroll
        for (int t = 0; t < 4; t++) {
            int idx = tid + t * 256;
            int row = idx >> 3, c4 = idx & 7;
            float4 v = make_float4(0.f, 0.f, 0.f, 0.f);
            if (m0 + row < Mrows)
                v = *(const float4*)(A + (size_t)(m0 + row) * DIM + k0 + c4 * 4);
            unsigned* p = As + row * SMSTRIDE + c4 * 4;
            p[0] = f2tf32(v.x); p[1] = f2tf32(v.y);
            p[2] = f2tf32(v.z); p[3] = f2tf32(v.w);
        }
        // B chunk: 32 k-rows x 128 n -> store transposed [n][k]
        #pragma unroll
        for (int t = 0; t < 4; t++) {
            int idx = tid + t * 256;
            int kr = idx & 31, c4 = idx >> 5;
            float4 v = *(const float4*)(g_W + (size_t)(k0 + kr) * YCOLS + n0 + c4 * 4);
            Bt[(c4 * 4 + 0) * SMSTRIDE + kr] = f2tf32(v.x);
            Bt[(c4 * 4 + 1) * SMSTRIDE + kr] = f2tf32(v.y);
            Bt[(c4 * 4 + 2) * SMSTRIDE + kr] = f2tf32(v.z);
            Bt[(c4 * 4 + 3) * SMSTRIDE + kr] = f2tf32(v.w);
        }
        __syncthreads();

        #pragma unroll
        for (int kk = 0; kk < 4; kk++) {
            unsigned a[2][4], b[8][2];
            #pragma unroll
            for (int mi = 0; mi < 2; mi++) {
                int br = warp_m * 32 + mi * 16;
                a[mi][0] = As[(br + g) * SMSTRIDE + kk * 8 + tig];
                a[mi][1] = As[(br + g + 8) * SMSTRIDE + kk * 8 + tig];
                a[mi][2] = As[(br + g) * SMSTRIDE + kk * 8 + tig + 4];
                a[mi][3] = As[(br + g + 8) * SMSTRIDE + kk * 8 + tig + 4];
            }
            #pragma unroll
            for (int ni = 0; ni < 8; ni++) {
                int bn = warp_n * 64 + ni * 8;
                b[ni][0] = Bt[(bn + g) * SMSTRIDE + kk * 8 + tig];
                b[ni][1] = Bt[(bn + g) * SMSTRIDE + kk * 8 + tig + 4];
            }
            #pragma unroll
            for (int mi = 0; mi < 2; mi++)
                #pragma unroll
                for (int ni = 0; ni < 8; ni++) {
                    asm volatile(
                        "mma.sync.aligned.m16n8k8.row.col.f32.tf32.tf32.f32 "
                        "{%0,%1,%2,%3}, {%4,%5,%6,%7}, {%8,%9}, {%0,%1,%2,%3};"
                        : "+f"(d[mi][ni][0]), "+f"(d[mi][ni][1]),
                          "+f"(d[mi][ni][2]), "+f"(d[mi][ni][3])
                        : "r"(a[mi][0]), "r"(a[mi][1]), "r"(a[mi][2]), "r"(a[mi][3]),
                          "r"(b[ni][0]), "r"(b[ni][1]));
                }
        }
        __syncthreads();
    }

    // store
    int bidx = blockIdx.y;
    if (bidx < NBASES) {
        // basis output: bf16, interleaved [node][d/4][basis][4]
        #pragma unroll
        for (int mi = 0; mi < 2; mi++) {
            int r0 = m0 + warp_m * 32 + mi * 16 + g;
            #pragma unroll
            for (int ni = 0; ni < 8; ni++) {
                int dd = warp_n * 64 + ni * 8 + tig * 2;   // output dim (0..127)
                size_t off = (size_t)r0 * (NBASES * DIM) + (dd >> 2) * 16 + bidx * 4 + (dd & 3);
                if (r0 < Mrows)
                    *(__nv_bfloat162*)(g_Yb + off) =
                        __floats2bfloat162_rn(d[mi][ni][0], d[mi][ni][1]);
                if (r0 + 8 < Mrows)
                    *(__nv_bfloat162*)(g_Yb + off + (size_t)8 * (NBASES * DIM)) =
                        __floats2bfloat162_rn(d[mi][ni][2], d[mi][ni][3]);
            }
        }
    } else {
        // root output: fp32 [node][128]
        #pragma unroll
        for (int mi = 0; mi < 2; mi++) {
            int r0 = m0 + warp_m * 32 + mi * 16 + g;
            #pragma unroll
            for (int ni = 0; ni < 8; ni++) {
                int dd = warp_n * 64 + ni * 8 + tig * 2;
                if (r0 < Mrows)
                    *(float2*)(g_Yr + (size_t)r0 * DIM + dd) =
                        make_float2(d[mi][ni][0], d[mi][ni][1]);
                if (r0 + 8 < Mrows)
                    *(float2*)(g_Yr + (size_t)(r0 + 8) * DIM + dd) =
                        make_float2(d[mi][ni][2], d[mi][ni][3]);
            }
        }
    }
}

// ---------------- edge message + aggregation ----------------
// one warp per edge; lane handles dims [lane*4, lane*4+3].
// Yb interleaved layout: per d-group of 4, 4 bases x 4 bf16 = 32 B -> 2 uint4 loads/lane.
__global__ void __launch_bounds__(256) k_edge(const int* __restrict__ ei,
                                              const int* __restrict__ etype,
                                              const float* __restrict__ enorm,
                                              const float* __restrict__ att) {
    int e = blockIdx.x * 8 + (threadIdx.x >> 5);
    if (e >= E_NUM) return;
    int lane = threadIdx.x & 31;

    int src = __ldg(ei + e);
    int dst = __ldg(ei + E_NUM + e);
    int t   = __ldg(etype + e);
    float nrm = __ldg(enorm + e);
    float4 c = __ldg((const float4*)att + t);
    float c0 = nrm * c.x, c1 = nrm * c.y, c2 = nrm * c.z, c3 = nrm * c.w;

    const uint4* Ys = (const uint4*)g_Yb + (size_t)src * 64;   // 64 uint4 per node
    uint4 v0 = Ys[lane * 2];       // basis 0 (8B) + basis 1 (8B)
    uint4 v1 = Ys[lane * 2 + 1];   // basis 2 + basis 3

    float2 b0l = __bfloat1622float2(*(const __nv_bfloat162*)&v0.x);
    float2 b0h = __bfloat1622float2(*(const __nv_bfloat162*)&v0.y);
    float2 b1l = __bfloat1622float2(*(const __nv_bfloat162*)&v0.z);
    float2 b1h = __bfloat1622float2(*(const __nv_bfloat162*)&v0.w);
    float2 b2l = __bfloat1622float2(*(const __nv_bfloat162*)&v1.x);
    float2 b2h = __bfloat1622float2(*(const __nv_bfloat162*)&v1.y);
    float2 b3l = __bfloat1622float2(*(const __nv_bfloat162*)&v1.z);
    float2 b3h = __bfloat1622float2(*(const __nv_bfloat162*)&v1.w);

    float4 m;
    m.x = c0 * b0l.x + c1 * b1l.x + c2 * b2l.x + c3 * b3l.x;
    m.y = c0 * b0l.y + c1 * b1l.y + c2 * b2l.y + c3 * b3l.y;
    m.z = c0 * b0h.x + c1 * b1h.x + c2 * b2h.x + c3 * b3h.x;
    m.w = c0 * b0h.y + c1 * b1h.y + c2 * b2h.y + c3 * b3h.y;

    float* out = g_agg + (size_t)dst * DIM + lane * 4;
    asm volatile("red.global.add.v4.f32 [%0], {%1,%2,%3,%4};"
                 :: "l"(out), "f"(m.x), "f"(m.y), "f"(m.z), "f"(m.w)
                 : "memory");
}

// ---------------- combine: Xnext = relu(agg*inv + Yroot + bias) ----------------
__global__ void k_combine(int obuf, const float* __restrict__ bias) {
    int idx = blockIdx.x * blockDim.x + threadIdx.x;   // float4 index
    if (idx >= N_ENT * (DIM / 4)) return;
    int n = idx >> 5, c4 = idx & 31;
    float inv = g_inv[n];
    float4 a = *(float4*)(g_agg + (size_t)n * DIM + c4 * 4);
    float4 r = *(const float4*)(g_Yr + (size_t)n * DIM + c4 * 4);
    float4 b = *(const float4*)(bias + c4 * 4);
    float4 o;
    o.x = fmaxf(a.x * inv + r.x + b.x, 0.f);
    o.y = fmaxf(a.y * inv + r.y + b.y, 0.f);
    o.z = fmaxf(a.z * inv + r.z + b.z, 0.f);
    o.w = fmaxf(a.w * inv + r.w + b.w, 0.f);
    *(float4*)(g_X[obuf] + (size_t)n * DIM + c4 * 4) = o;
}

// ---------------- relation path (tiny) ----------------
__global__ void k_relT(const float* __restrict__ DAD, const float* __restrict__ rctx) {
    int idx = blockIdx.x * blockDim.x + threadIdx.x;
    if (idx >= NREL * DIM) return;
    int r = idx >> 7, o = idx & 127;
    float s = 0.f;
    for (int k = 0; k < NREL; k++)
        s += DAD[r * NREL + k] * rctx[k * DIM + o];
    g_T[idx] = s;
}

__global__ void k_relR(const float* __restrict__ W) {
    int idx = blockIdx.x * blockDim.x + threadIdx.x;
    if (idx >= NREL * DIM) return;
    int r = idx >> 7, o = idx & 127;
    float s = 0.f;
    for (int k = 0; k < DIM; k++)
        s += g_T[r * DIM + k] * W[k * DIM + o];
    g_R[idx] = fmaxf(s, 0.f);
}

// ---------------- final gated gather ----------------
__global__ void k_out(const int* __restrict__ samples,
                      const float* __restrict__ ent_emb,
                      const float* __restrict__ rel_emb,
                      const float* __restrict__ gate_e,
                      const float* __restrict__ gate_r,
                      int x2buf, float* __restrict__ out) {
    int idx = blockIdx.x * blockDim.x + threadIdx.x;
    if (idx >= S_NUM * DIM) return;
    int s = idx >> 7, d = idx & 127;
    int h = samples[s * 3 + 0];
    int r = samples[s * 3 + 1];
    int t = samples[s * 3 + 2];
    float ge = 1.0f / (1.0f + expf(-gate_e[d]));
    float gr = 1.0f / (1.0f + expf(-gate_r[d]));
    const float* X2 = g_X[x2buf];
    out[idx] = ge * ent_emb[(size_t)h * DIM + d] + (1.0f - ge) * X2[(size_t)h * DIM + d];
    out[S_NUM * DIM + idx] = gr * rel_emb[(size_t)r * DIM + d] + (1.0f - gr) * g_R[(size_t)r * DIM + d];
    out[2 * S_NUM * DIM + idx] = ge * ent_emb[(size_t)t * DIM + d] + (1.0f - ge) * X2[(size_t)t * DIM + d];
}

// ---------------- launch ----------------
extern "C" void kernel_launch(void* const* d_in, const int* in_sizes, int n_in,
                              void* d_out, int out_size) {
    const int*   entity    = (const int*)d_in[0];
    const int*   edge_index= (const int*)d_in[1];
    const int*   edge_type = (const int*)d_in[2];
    const float* edge_norm = (const float*)d_in[3];
    const int*   samples   = (const int*)d_in[4];
    const float* DAD       = (const float*)d_in[5];
    const float* ent_emb   = (const float*)d_in[6];
    const float* rel_emb   = (const float*)d_in[7];
    const float* ectx      = (const float*)d_in[8];
    const float* rctx      = (const float*)d_in[9];
    const float* gcnW      = (const float*)d_in[10];
    const float* gate_e    = (const float*)d_in[11];
    const float* gate_r    = (const float*)d_in[12];
    const float* basis1    = (const float*)d_in[13];
    const float* att1      = (const float*)d_in[14];
    const float* root1     = (const float*)d_in[15];
    const float* bias1     = (const float*)d_in[16];
    const float* basis2    = (const float*)d_in[17];
    const float* att2      = (const float*)d_in[18];
    const float* root2     = (const float*)d_in[19];
    const float* bias2     = (const float*)d_in[20];
    float* out = (float*)d_out;

    const int THR = 256;
    dim3 gemm_grid((N_ENT + 127) / 128, YCOLS / 128);

    // degree counts (shared by both layers)
    k_zero_cnt<<<(N_ENT + THR - 1) / THR, THR>>>();
    k_count<<<(E_NUM + THR - 1) / THR, THR>>>(edge_index);
    k_inv<<<(N_ENT + THR - 1) / THR, THR>>>();

    // initial features
    k_gather<<<(N_ENT * (DIM / 4) + THR - 1) / THR, THR>>>(entity, ectx);

    // ---- layer 1 ----
    k_pack<<<(DIM * YCOLS + THR - 1) / THR, THR>>>(basis1, root1);
    k_gemm_tf32<<<gemm_grid, THR>>>(0, N_ENT);
    k_zero_agg<<<(N_ENT * (DIM / 4) + THR - 1) / THR, THR>>>();
    k_edge<<<(E_NUM + 7) / 8, THR>>>(edge_index, edge_type, edge_norm, att1);
    k_combine<<<(N_ENT * (DIM / 4) + THR - 1) / THR, THR>>>(1, bias1);

    // ---- layer 2 ----
    k_pack<<<(DIM * YCOLS + THR - 1) / THR, THR>>>(basis2, root2);
    k_gemm_tf32<<<gemm_grid, THR>>>(1, N_ENT);
    k_zero_agg<<<(N_ENT * (DIM / 4) + THR - 1) / THR, THR>>>();
    k_edge<<<(E_NUM + 7) / 8, THR>>>(edge_index, edge_type, edge_norm, att2);
    k_combine<<<(N_ENT * (DIM / 4) + THR - 1) / THR, THR>>>(0, bias2);

    // ---- relation path ----
    k_relT<<<(NREL * DIM + THR - 1) / THR, THR>>>(DAD, rctx);
    k_relR<<<(NREL * DIM + THR - 1) / THR, THR>>>(gcnW);

    // ---- output ----
    k_out<<<(S_NUM * DIM + THR - 1) / THR, THR>>>(samples, ent_emb, rel_emb,
                                                  gate_e, gate_r, 0, out);
}